// round 1
// baseline (speedup 1.0000x reference)
#include <cuda_runtime.h>
#include <math.h>

#define SQ      2048
#define Dm      512
#define NHEADS  8
#define HDIM    64
#define MTOT    8192        // B*Sq = 4*2048
#define ATT_SCALE 0.125f    // 1/sqrt(64)

// Scratch (allocation-free rule: __device__ globals)
__device__ float g_Q [MTOT * Dm];
__device__ float g_K [MTOT * Dm];
__device__ float g_V [MTOT * Dm];
__device__ float g_O1[MTOT * Dm];

// ---------------------------------------------------------------------------
// GEMM: out[m][n] = X[m][:] . W[n][:] + bias[n]     (X [M,512], W [512,512])
// MODE 0: out = acc + bias
// MODE 1: out = res[m][n] + relu(acc + bias)
// 128x128 block tile, BK=8, 256 threads, 8x8 register micro-tile.
// ---------------------------------------------------------------------------
template<int MODE>
__global__ void __launch_bounds__(256) gemm_bias_kernel(
    const float* __restrict__ X, const float* __restrict__ W,
    const float* __restrict__ bias, const float* __restrict__ res,
    float* __restrict__ out)
{
    __shared__ float As[8][128];
    __shared__ float Bs[8][128];

    const int tid  = threadIdx.x;
    const int m0   = blockIdx.x * 128;
    const int n0   = blockIdx.y * 128;
    const int tc   = tid & 15;
    const int tr   = tid >> 4;
    const int lrow = tid >> 1;          // 0..127
    const int lk4  = (tid & 1) * 4;     // 0 or 4

    const float* Xp = X + (size_t)(m0 + lrow) * Dm + lk4;
    const float* Wp = W + (size_t)(n0 + lrow) * Dm + lk4;

    float acc[8][8];
#pragma unroll
    for (int i = 0; i < 8; i++)
#pragma unroll
        for (int j = 0; j < 8; j++) acc[i][j] = 0.f;

    for (int k0 = 0; k0 < Dm; k0 += 8) {
        float4 av = *(const float4*)(Xp + k0);
        float4 bv = *(const float4*)(Wp + k0);
        __syncthreads();
        As[lk4 + 0][lrow] = av.x; As[lk4 + 1][lrow] = av.y;
        As[lk4 + 2][lrow] = av.z; As[lk4 + 3][lrow] = av.w;
        Bs[lk4 + 0][lrow] = bv.x; Bs[lk4 + 1][lrow] = bv.y;
        Bs[lk4 + 2][lrow] = bv.z; Bs[lk4 + 3][lrow] = bv.w;
        __syncthreads();
#pragma unroll
        for (int k = 0; k < 8; k++) {
            float a[8], b[8];
            *(float4*)(a)     = *(const float4*)&As[k][tr * 8];
            *(float4*)(a + 4) = *(const float4*)&As[k][tr * 8 + 4];
            *(float4*)(b)     = *(const float4*)&Bs[k][tc * 8];
            *(float4*)(b + 4) = *(const float4*)&Bs[k][tc * 8 + 4];
#pragma unroll
            for (int i = 0; i < 8; i++)
#pragma unroll
                for (int j = 0; j < 8; j++)
                    acc[i][j] += a[i] * b[j];
        }
    }

#pragma unroll
    for (int i = 0; i < 8; i++) {
        const int m = m0 + tr * 8 + i;
#pragma unroll
        for (int j4 = 0; j4 < 8; j4 += 4) {
            const int n = n0 + tc * 8 + j4;
            float4 r;
            r.x = acc[i][j4 + 0] + bias[n + 0];
            r.y = acc[i][j4 + 1] + bias[n + 1];
            r.z = acc[i][j4 + 2] + bias[n + 2];
            r.w = acc[i][j4 + 3] + bias[n + 3];
            if (MODE == 1) {
                const float4 rv = *(const float4*)&res[(size_t)m * Dm + n];
                r.x = rv.x + fmaxf(r.x, 0.f);
                r.y = rv.y + fmaxf(r.y, 0.f);
                r.z = rv.z + fmaxf(r.z, 0.f);
                r.w = rv.w + fmaxf(r.w, 0.f);
            }
            *(float4*)&out[(size_t)m * Dm + n] = r;
        }
    }
}

// ---------------------------------------------------------------------------
// Flash attention (fp32, online softmax) + q-residual epilogue.
// grid: (Sq/128, B*H). block: 256 threads. 128 queries x 128 kv per tile.
// smem layouts: Qs[d][r] (64x128), Ks[d][c] (64x128), Ss[c][r] (128x128),
//               Vs[c][d] (128x64), row stats m/l/alpha [128].
// out1[b,q,h*64+d] = q_proj + O/l
// ---------------------------------------------------------------------------
#define FLASH_SMEM_FLOATS (64*128 + 64*128 + 128*128 + 128*64 + 3*128)
#define FLASH_SMEM_BYTES  (FLASH_SMEM_FLOATS * 4)

__global__ void __launch_bounds__(256) flash_kernel(
    const float* __restrict__ gQ, const float* __restrict__ gK,
    const float* __restrict__ gV, float* __restrict__ gO1)
{
    extern __shared__ float sm[];
    float* Qs   = sm;                  // [64][128]  Qs[d*128 + r]
    float* Ks   = Qs + 64 * 128;       // [64][128]  Ks[d*128 + c]
    float* Ss   = Ks + 64 * 128;       // [128][128] Ss[c*128 + r]
    float* Vs   = Ss + 128 * 128;      // [128][64]  Vs[c*64 + d]
    float* mrow = Vs + 128 * 64;       // [128]
    float* lsum = mrow + 128;          // [128]
    float* arow = lsum + 128;          // [128]

    const int tid = threadIdx.x;
    const int bh  = blockIdx.y;
    const int b   = bh / NHEADS;
    const int h   = bh % NHEADS;
    const int q0  = blockIdx.x * 128;

    const float* Qg = gQ + ((size_t)b * SQ + q0) * Dm + h * HDIM;
    const float* Kg = gK + (size_t)b * SQ * Dm + h * HDIM;
    const float* Vg = gV + (size_t)b * SQ * Dm + h * HDIM;

    const int tc = tid & 15;
    const int tr = tid >> 4;

    // Load Q tile (128 rows x 64 d), transpose into Qs[d][r]
#pragma unroll
    for (int i = 0; i < 8; i++) {
        int l  = tid + 256 * i;     // float4 index, 2048 total
        int r  = l >> 4;            // 16 float4 per row
        int c4 = (l & 15) * 4;
        float4 v = *(const float4*)(Qg + (size_t)r * Dm + c4);
        Qs[(c4 + 0) * 128 + r] = v.x;
        Qs[(c4 + 1) * 128 + r] = v.y;
        Qs[(c4 + 2) * 128 + r] = v.z;
        Qs[(c4 + 3) * 128 + r] = v.w;
    }
    if (tid < 128) { mrow[tid] = -1e30f; lsum[tid] = 0.f; }

    float oacc[8][4];
#pragma unroll
    for (int i = 0; i < 8; i++)
#pragma unroll
        for (int j = 0; j < 4; j++) oacc[i][j] = 0.f;

    __syncthreads();

    for (int kv0 = 0; kv0 < SQ; kv0 += 128) {
        // Load K (transposed) and V (natural) tiles
#pragma unroll
        for (int i = 0; i < 8; i++) {
            int l  = tid + 256 * i;
            int r  = l >> 4;
            int c4 = (l & 15) * 4;
            float4 kv4 = *(const float4*)(Kg + (size_t)(kv0 + r) * Dm + c4);
            Ks[(c4 + 0) * 128 + r] = kv4.x;
            Ks[(c4 + 1) * 128 + r] = kv4.y;
            Ks[(c4 + 2) * 128 + r] = kv4.z;
            Ks[(c4 + 3) * 128 + r] = kv4.w;
            float4 vv = *(const float4*)(Vg + (size_t)(kv0 + r) * Dm + c4);
            *(float4*)&Vs[r * 64 + c4] = vv;
        }
        __syncthreads();

        // S[r][c] = sum_d Qs[d][r] * Ks[d][c]
        float sacc[8][8];
#pragma unroll
        for (int i = 0; i < 8; i++)
#pragma unroll
            for (int j = 0; j < 8; j++) sacc[i][j] = 0.f;

#pragma unroll 8
        for (int d = 0; d < HDIM; d++) {
            float a[8], bb[8];
            *(float4*)(a)      = *(const float4*)&Qs[d * 128 + tr * 8];
            *(float4*)(a + 4)  = *(const float4*)&Qs[d * 128 + tr * 8 + 4];
            *(float4*)(bb)     = *(const float4*)&Ks[d * 128 + tc * 8];
            *(float4*)(bb + 4) = *(const float4*)&Ks[d * 128 + tc * 8 + 4];
#pragma unroll
            for (int i = 0; i < 8; i++)
#pragma unroll
                for (int j = 0; j < 8; j++)
                    sacc[i][j] += a[i] * bb[j];
        }

        // Write scaled S into Ss[c][r]
#pragma unroll
        for (int j = 0; j < 8; j++) {
            const int c = tc * 8 + j;
            float4 v0, v1;
            v0.x = sacc[0][j] * ATT_SCALE; v0.y = sacc[1][j] * ATT_SCALE;
            v0.z = sacc[2][j] * ATT_SCALE; v0.w = sacc[3][j] * ATT_SCALE;
            v1.x = sacc[4][j] * ATT_SCALE; v1.y = sacc[5][j] * ATT_SCALE;
            v1.z = sacc[6][j] * ATT_SCALE; v1.w = sacc[7][j] * ATT_SCALE;
            *(float4*)&Ss[c * 128 + tr * 8]     = v0;
            *(float4*)&Ss[c * 128 + tr * 8 + 4] = v1;
        }
        __syncthreads();

        // Online-softmax row pass (one thread per query row)
        if (tid < 128) {
            const int r = tid;
            float mo = mrow[r];
            float mx = mo;
            for (int c = 0; c < 128; c++)
                mx = fmaxf(mx, Ss[c * 128 + r]);
            float al = __expf(mo - mx);
            float s = 0.f;
            for (int c = 0; c < 128; c++) {
                float p = __expf(Ss[c * 128 + r] - mx);
                Ss[c * 128 + r] = p;
                s += p;
            }
            mrow[r] = mx;
            lsum[r] = lsum[r] * al + s;
            arow[r] = al;
        }
        __syncthreads();

        // Rescale O and accumulate P @ V
        float alr[8];
#pragma unroll
        for (int i = 0; i < 8; i++) alr[i] = arow[tr * 8 + i];
#pragma unroll
        for (int i = 0; i < 8; i++)
#pragma unroll
            for (int j = 0; j < 4; j++) oacc[i][j] *= alr[i];

#pragma unroll 8
        for (int c = 0; c < 128; c++) {
            float p[8];
            *(float4*)(p)     = *(const float4*)&Ss[c * 128 + tr * 8];
            *(float4*)(p + 4) = *(const float4*)&Ss[c * 128 + tr * 8 + 4];
            float4 vv = *(const float4*)&Vs[c * 64 + tc * 4];
#pragma unroll
            for (int i = 0; i < 8; i++) {
                oacc[i][0] += p[i] * vv.x;
                oacc[i][1] += p[i] * vv.y;
                oacc[i][2] += p[i] * vv.z;
                oacc[i][3] += p[i] * vv.w;
            }
        }
        __syncthreads();   // protect Ks/Ss/Vs/stats for next iteration
    }

    // Epilogue: out1 = q_proj + O/l    (thread covers rows tr*8..+7, d = tc*4..+3)
    float* Og = gO1 + ((size_t)b * SQ + q0) * Dm + h * HDIM;
#pragma unroll
    for (int i = 0; i < 8; i++) {
        const int r = tr * 8 + i;
        const float linv = 1.f / lsum[r];
        float4 o;
        o.x = Qs[(tc * 4 + 0) * 128 + r] + oacc[i][0] * linv;
        o.y = Qs[(tc * 4 + 1) * 128 + r] + oacc[i][1] * linv;
        o.z = Qs[(tc * 4 + 2) * 128 + r] + oacc[i][2] * linv;
        o.w = Qs[(tc * 4 + 3) * 128 + r] + oacc[i][3] * linv;
        *(float4*)&Og[(size_t)r * Dm + tc * 4] = o;
    }
}

// ---------------------------------------------------------------------------
extern "C" void kernel_launch(void* const* d_in, const int* in_sizes, int n_in,
                              void* d_out, int out_size)
{
    const float* query = (const float*)d_in[0];
    const float* keyv  = (const float*)d_in[1];
    const float* Wq    = (const float*)d_in[2];
    const float* bq    = (const float*)d_in[3];
    const float* Wk    = (const float*)d_in[4];
    const float* bk    = (const float*)d_in[5];
    const float* Wv    = (const float*)d_in[6];
    const float* bv    = (const float*)d_in[7];
    const float* Wo    = (const float*)d_in[8];
    const float* bo    = (const float*)d_in[9];
    float* out = (float*)d_out;

    float *qb, *kb, *vb, *o1;
    cudaGetSymbolAddress((void**)&qb, g_Q);
    cudaGetSymbolAddress((void**)&kb, g_K);
    cudaGetSymbolAddress((void**)&vb, g_V);
    cudaGetSymbolAddress((void**)&o1, g_O1);

    cudaFuncSetAttribute(flash_kernel,
                         cudaFuncAttributeMaxDynamicSharedMemorySize,
                         FLASH_SMEM_BYTES);

    dim3 gg(MTOT / 128, Dm / 128);   // (64, 4)
    gemm_bias_kernel<0><<<gg, 256>>>(query, Wq, bq, nullptr, qb);
    gemm_bias_kernel<0><<<gg, 256>>>(keyv,  Wk, bk, nullptr, kb);
    gemm_bias_kernel<0><<<gg, 256>>>(keyv,  Wv, bv, nullptr, vb);

    dim3 ga(SQ / 128, 4 * NHEADS);   // (16, 32)
    flash_kernel<<<ga, 256, FLASH_SMEM_BYTES>>>(qb, kb, vb, o1);

    gemm_bias_kernel<1><<<gg, 256>>>(o1, Wo, bo, o1, out);
}

// round 2
// speedup vs baseline: 2.5807x; 2.5807x over previous
#include <cuda_runtime.h>
#include <math.h>

#define SQ      2048
#define Dm      512
#define NHEADS  8
#define HDIM    64
#define MTOT    8192
#define ATT_SCALE 0.125f
#define LOG2E   1.44269504f

__device__ float g_Q [MTOT * Dm];
__device__ float g_K [MTOT * Dm];
__device__ float g_V [MTOT * Dm];
__device__ float g_O1[MTOT * Dm];

__device__ __forceinline__ unsigned f2tf(float x) {
    unsigned u;
    asm("cvt.rna.tf32.f32 %0, %1;" : "=r"(u) : "f"(x));
    return u;
}

__device__ __forceinline__ void mma8(float* c, unsigned a0, unsigned a1,
                                     unsigned a2, unsigned a3,
                                     unsigned b0, unsigned b1) {
    asm volatile(
        "mma.sync.aligned.m16n8k8.row.col.f32.tf32.tf32.f32 "
        "{%0,%1,%2,%3}, {%4,%5,%6,%7}, {%8,%9}, {%0,%1,%2,%3};\n"
        : "+f"(c[0]), "+f"(c[1]), "+f"(c[2]), "+f"(c[3])
        : "r"(a0), "r"(a1), "r"(a2), "r"(a3), "r"(b0), "r"(b1));
}

// ---------------------------------------------------------------------------
// tf32 tensor-core GEMM: out[m][n] = X[m][:].W[n][:] + bias[n]
// MODE 0: out = acc + bias ; MODE 1: out = res + relu(acc + bias)
// 128x128 block, 8 warps (warp = 16-row strip x 128 cols), K staged 32.
// ---------------------------------------------------------------------------
template<int MODE>
__global__ void __launch_bounds__(256) gemm_tc(
    const float* __restrict__ X, const float* __restrict__ W,
    const float* __restrict__ bias, const float* __restrict__ res,
    float* __restrict__ out)
{
    __shared__ unsigned Xs[128][36];   // [m][k]  (stride 36: frag LDS conflict-free)
    __shared__ unsigned Wt[32][136];   // [k][n]  (stride 136 = 8 mod 32)

    const int tid  = threadIdx.x;
    const int wid  = tid >> 5;
    const int lane = tid & 31;
    const int g    = lane >> 2;
    const int tig  = lane & 3;
    const int m0   = blockIdx.x * 128;
    const int n0   = blockIdx.y * 128;

    float acc[16][4];
#pragma unroll
    for (int i = 0; i < 16; i++)
#pragma unroll
        for (int j = 0; j < 4; j++) acc[i][j] = 0.f;

    for (int k0 = 0; k0 < Dm; k0 += 32) {
        __syncthreads();
#pragma unroll
        for (int i = 0; i < 4; i++) {
            int idx = tid + 256 * i;
            int r   = idx >> 3;
            int c4  = (idx & 7) * 4;
            float4 xv = *(const float4*)&X[(size_t)(m0 + r) * Dm + k0 + c4];
            *(uint4*)&Xs[r][c4] =
                make_uint4(f2tf(xv.x), f2tf(xv.y), f2tf(xv.z), f2tf(xv.w));
            float4 wv = *(const float4*)&W[(size_t)(n0 + r) * Dm + k0 + c4];
            Wt[c4 + 0][r] = f2tf(wv.x);
            Wt[c4 + 1][r] = f2tf(wv.y);
            Wt[c4 + 2][r] = f2tf(wv.z);
            Wt[c4 + 3][r] = f2tf(wv.w);
        }
        __syncthreads();

#pragma unroll
        for (int kk = 0; kk < 4; kk++) {
            const int kb = kk * 8;
            unsigned a0 = Xs[16 * wid + g][kb + tig];
            unsigned a1 = Xs[16 * wid + 8 + g][kb + tig];
            unsigned a2 = Xs[16 * wid + g][kb + tig + 4];
            unsigned a3 = Xs[16 * wid + 8 + g][kb + tig + 4];
#pragma unroll
            for (int nt = 0; nt < 16; nt++) {
                unsigned b0 = Wt[kb + tig][nt * 8 + g];
                unsigned b1 = Wt[kb + tig + 4][nt * 8 + g];
                mma8(acc[nt], a0, a1, a2, a3, b0, b1);
            }
        }
    }

    const int r0 = m0 + 16 * wid + g;
    const int r1 = r0 + 8;
#pragma unroll
    for (int nt = 0; nt < 16; nt++) {
        const int n = n0 + nt * 8 + 2 * tig;
        float2 bz = *(const float2*)&bias[n];
        float2 o0, o1;
        o0.x = acc[nt][0] + bz.x; o0.y = acc[nt][1] + bz.y;
        o1.x = acc[nt][2] + bz.x; o1.y = acc[nt][3] + bz.y;
        if (MODE == 1) {
            float2 q0 = *(const float2*)&res[(size_t)r0 * Dm + n];
            float2 q1 = *(const float2*)&res[(size_t)r1 * Dm + n];
            o0.x = q0.x + fmaxf(o0.x, 0.f); o0.y = q0.y + fmaxf(o0.y, 0.f);
            o1.x = q1.x + fmaxf(o1.x, 0.f); o1.y = q1.y + fmaxf(o1.y, 0.f);
        }
        *(float2*)&out[(size_t)r0 * Dm + n] = o0;
        *(float2*)&out[(size_t)r1 * Dm + n] = o1;
    }
}

// ---------------------------------------------------------------------------
// tf32 tensor-core flash attention + q-residual epilogue.
// 128q x 128kv tiles, 8 warps, warp owns 16 query rows; softmax stats in regs.
// ---------------------------------------------------------------------------
#define QS_STRIDE 68
#define KT_STRIDE 136
#define VS_STRIDE 72
#define PS_STRIDE 132
#define QS_BASE 0
#define KT_BASE (QS_BASE + 128 * QS_STRIDE)
#define VS_BASE (KT_BASE + 64 * KT_STRIDE)
#define PS_BASE (VS_BASE + 128 * VS_STRIDE)
#define FLASH_SMEM_U32 (PS_BASE + 128 * PS_STRIDE)
#define FLASH_SMEM_BYTES (FLASH_SMEM_U32 * 4)

__global__ void __launch_bounds__(256) flash_tc(
    const float* __restrict__ gQ, const float* __restrict__ gK,
    const float* __restrict__ gV, float* __restrict__ gO1)
{
    extern __shared__ unsigned sm[];
    unsigned* Qs = sm + QS_BASE;   // [128][68]  q tf32, [m][d]
    unsigned* Kt = sm + KT_BASE;   // [64][136]  k tf32, [d][kv]
    unsigned* Vs = sm + VS_BASE;   // [128][72]  v tf32, [kv][d]
    unsigned* Ps = sm + PS_BASE;   // [128][132] p tf32, [m][kv]

    const int tid  = threadIdx.x;
    const int wid  = tid >> 5;
    const int lane = tid & 31;
    const int g    = lane >> 2;
    const int tig  = lane & 3;

    const int bh = blockIdx.y;
    const int b  = bh / NHEADS;
    const int h  = bh % NHEADS;
    const int q0 = blockIdx.x * 128;

    const float* Qg = gQ + ((size_t)b * SQ + q0) * Dm + h * HDIM;
    const float* Kg = gK + (size_t)b * SQ * Dm + h * HDIM;
    const float* Vg = gV + (size_t)b * SQ * Dm + h * HDIM;

    // Stage Q tile once (tf32)
#pragma unroll
    for (int i = 0; i < 8; i++) {
        int idx = tid + 256 * i;
        int r   = idx >> 4;
        int c4  = (idx & 15) * 4;
        float4 v = *(const float4*)&Qg[(size_t)r * Dm + c4];
        *(uint4*)&Qs[r * QS_STRIDE + c4] =
            make_uint4(f2tf(v.x), f2tf(v.y), f2tf(v.z), f2tf(v.w));
    }

    float m0r = -1e30f, m1r = -1e30f, l0 = 0.f, l1 = 0.f;
    float oacc[8][4];
#pragma unroll
    for (int i = 0; i < 8; i++)
#pragma unroll
        for (int j = 0; j < 4; j++) oacc[i][j] = 0.f;

    const float SCL = ATT_SCALE * LOG2E;
    const int rw0 = 16 * wid + g;      // warp-local query rows
    const int rw1 = rw0 + 8;

    for (int kv0 = 0; kv0 < SQ; kv0 += 128) {
        __syncthreads();
#pragma unroll
        for (int i = 0; i < 8; i++) {
            int idx = tid + 256 * i;
            int r   = idx >> 4;
            int c4  = (idx & 15) * 4;
            float4 kv = *(const float4*)&Kg[(size_t)(kv0 + r) * Dm + c4];
            Kt[(c4 + 0) * KT_STRIDE + r] = f2tf(kv.x);
            Kt[(c4 + 1) * KT_STRIDE + r] = f2tf(kv.y);
            Kt[(c4 + 2) * KT_STRIDE + r] = f2tf(kv.z);
            Kt[(c4 + 3) * KT_STRIDE + r] = f2tf(kv.w);
            float4 vv = *(const float4*)&Vg[(size_t)(kv0 + r) * Dm + c4];
            *(uint4*)&Vs[r * VS_STRIDE + c4] =
                make_uint4(f2tf(vv.x), f2tf(vv.y), f2tf(vv.z), f2tf(vv.w));
        }
        __syncthreads();

        // S = Q K^T  (warp rows x 128 kv)
        float sacc[16][4];
#pragma unroll
        for (int i = 0; i < 16; i++)
#pragma unroll
            for (int j = 0; j < 4; j++) sacc[i][j] = 0.f;

#pragma unroll
        for (int ks = 0; ks < 8; ks++) {
            const int kb = ks * 8;
            unsigned a0 = Qs[rw0 * QS_STRIDE + kb + tig];
            unsigned a1 = Qs[rw1 * QS_STRIDE + kb + tig];
            unsigned a2 = Qs[rw0 * QS_STRIDE + kb + tig + 4];
            unsigned a3 = Qs[rw1 * QS_STRIDE + kb + tig + 4];
#pragma unroll
            for (int nt = 0; nt < 16; nt++) {
                unsigned b0 = Kt[(kb + tig) * KT_STRIDE + nt * 8 + g];
                unsigned b1 = Kt[(kb + tig + 4) * KT_STRIDE + nt * 8 + g];
                mma8(sacc[nt], a0, a1, a2, a3, b0, b1);
            }
        }

        // Online softmax (log2 domain). Row reduce over quad lanes (xor 1,2).
        float mx0 = -1e30f, mx1 = -1e30f;
#pragma unroll
        for (int nt = 0; nt < 16; nt++) {
            mx0 = fmaxf(mx0, fmaxf(sacc[nt][0], sacc[nt][1]));
            mx1 = fmaxf(mx1, fmaxf(sacc[nt][2], sacc[nt][3]));
        }
        mx0 *= SCL; mx1 *= SCL;
        mx0 = fmaxf(mx0, __shfl_xor_sync(0xffffffffu, mx0, 1));
        mx0 = fmaxf(mx0, __shfl_xor_sync(0xffffffffu, mx0, 2));
        mx1 = fmaxf(mx1, __shfl_xor_sync(0xffffffffu, mx1, 1));
        mx1 = fmaxf(mx1, __shfl_xor_sync(0xffffffffu, mx1, 2));

        float mn0 = fmaxf(m0r, mx0), mn1 = fmaxf(m1r, mx1);
        float al0 = exp2f(m0r - mn0), al1 = exp2f(m1r - mn1);
        m0r = mn0; m1r = mn1;

        float sum0 = 0.f, sum1 = 0.f;
#pragma unroll
        for (int nt = 0; nt < 16; nt++) {
            float p00 = exp2f(sacc[nt][0] * SCL - m0r);
            float p01 = exp2f(sacc[nt][1] * SCL - m0r);
            float p10 = exp2f(sacc[nt][2] * SCL - m1r);
            float p11 = exp2f(sacc[nt][3] * SCL - m1r);
            sum0 += p00 + p01;
            sum1 += p10 + p11;
            const int cc = nt * 8 + 2 * tig;
            *(uint2*)&Ps[rw0 * PS_STRIDE + cc] = make_uint2(f2tf(p00), f2tf(p01));
            *(uint2*)&Ps[rw1 * PS_STRIDE + cc] = make_uint2(f2tf(p10), f2tf(p11));
        }
        sum0 += __shfl_xor_sync(0xffffffffu, sum0, 1);
        sum0 += __shfl_xor_sync(0xffffffffu, sum0, 2);
        sum1 += __shfl_xor_sync(0xffffffffu, sum1, 1);
        sum1 += __shfl_xor_sync(0xffffffffu, sum1, 2);
        l0 = l0 * al0 + sum0;
        l1 = l1 * al1 + sum1;

#pragma unroll
        for (int nt = 0; nt < 8; nt++) {
            oacc[nt][0] *= al0; oacc[nt][1] *= al0;
            oacc[nt][2] *= al1; oacc[nt][3] *= al1;
        }
        __syncwarp();

        // O += P V   (warp rows x 64 d, k over 128 kv)
#pragma unroll
        for (int ks = 0; ks < 16; ks++) {
            const int kb = ks * 8;
            unsigned a0 = Ps[rw0 * PS_STRIDE + kb + tig];
            unsigned a1 = Ps[rw1 * PS_STRIDE + kb + tig];
            unsigned a2 = Ps[rw0 * PS_STRIDE + kb + tig + 4];
            unsigned a3 = Ps[rw1 * PS_STRIDE + kb + tig + 4];
#pragma unroll
            for (int nt = 0; nt < 8; nt++) {
                unsigned b0 = Vs[(kb + tig) * VS_STRIDE + nt * 8 + g];
                unsigned b1 = Vs[(kb + tig + 4) * VS_STRIDE + nt * 8 + g];
                mma8(oacc[nt], a0, a1, a2, a3, b0, b1);
            }
        }
        __syncwarp();
    }

    // Epilogue: out1 = q(fp32) + O/l
    float* Og = gO1 + ((size_t)b * SQ + q0) * Dm + h * HDIM;
    const float li0 = 1.f / l0, li1 = 1.f / l1;
#pragma unroll
    for (int nt = 0; nt < 8; nt++) {
        const int c = nt * 8 + 2 * tig;
        float2 q0v = *(const float2*)&Qg[(size_t)rw0 * Dm + c];
        float2 q1v = *(const float2*)&Qg[(size_t)rw1 * Dm + c];
        float2 o0, o1;
        o0.x = q0v.x + oacc[nt][0] * li0;
        o0.y = q0v.y + oacc[nt][1] * li0;
        o1.x = q1v.x + oacc[nt][2] * li1;
        o1.y = q1v.y + oacc[nt][3] * li1;
        *(float2*)&Og[(size_t)rw0 * Dm + c] = o0;
        *(float2*)&Og[(size_t)rw1 * Dm + c] = o1;
    }
}

// ---------------------------------------------------------------------------
extern "C" void kernel_launch(void* const* d_in, const int* in_sizes, int n_in,
                              void* d_out, int out_size)
{
    const float* query = (const float*)d_in[0];
    const float* keyv  = (const float*)d_in[1];
    const float* Wq    = (const float*)d_in[2];
    const float* bq    = (const float*)d_in[3];
    const float* Wk    = (const float*)d_in[4];
    const float* bk    = (const float*)d_in[5];
    const float* Wv    = (const float*)d_in[6];
    const float* bv    = (const float*)d_in[7];
    const float* Wo    = (const float*)d_in[8];
    const float* bo    = (const float*)d_in[9];
    float* out = (float*)d_out;

    float *qb, *kb, *vb, *o1;
    cudaGetSymbolAddress((void**)&qb, g_Q);
    cudaGetSymbolAddress((void**)&kb, g_K);
    cudaGetSymbolAddress((void**)&vb, g_V);
    cudaGetSymbolAddress((void**)&o1, g_O1);

    cudaFuncSetAttribute(flash_tc,
                         cudaFuncAttributeMaxDynamicSharedMemorySize,
                         FLASH_SMEM_BYTES);

    dim3 gg(MTOT / 128, Dm / 128);   // (64, 4)
    gemm_tc<0><<<gg, 256>>>(query, Wq, bq, nullptr, qb);
    gemm_tc<0><<<gg, 256>>>(keyv,  Wk, bk, nullptr, kb);
    gemm_tc<0><<<gg, 256>>>(keyv,  Wv, bv, nullptr, vb);

    dim3 ga(SQ / 128, 4 * NHEADS);   // (16, 32)
    flash_tc<<<ga, 256, FLASH_SMEM_BYTES>>>(qb, kb, vb, o1);

    gemm_tc<1><<<gg, 256>>>(o1, Wo, bo, o1, out);
}

// round 3
// speedup vs baseline: 3.9962x; 1.5485x over previous
#include <cuda_runtime.h>
#include <math.h>

#define SQ      2048
#define Dm      512
#define NHEADS  8
#define HDIM    64
#define MTOT    8192
#define ATT_SCALE 0.125f
#define LOG2E   1.44269504f

__device__ float g_Q [MTOT * Dm];
__device__ float g_K [MTOT * Dm];
__device__ float g_V [MTOT * Dm];
__device__ float g_O1[MTOT * Dm];

__device__ __forceinline__ unsigned f2tf(float x) {
    unsigned u;
    asm("cvt.rna.tf32.f32 %0, %1;" : "=r"(u) : "f"(x));
    return u;
}

__device__ __forceinline__ void mma8(float* c, unsigned a0, unsigned a1,
                                     unsigned a2, unsigned a3,
                                     unsigned b0, unsigned b1) {
    asm volatile(
        "mma.sync.aligned.m16n8k8.row.col.f32.tf32.tf32.f32 "
        "{%0,%1,%2,%3}, {%4,%5,%6,%7}, {%8,%9}, {%0,%1,%2,%3};\n"
        : "+f"(c[0]), "+f"(c[1]), "+f"(c[2]), "+f"(c[3])
        : "r"(a0), "r"(a1), "r"(a2), "r"(a3), "r"(b0), "r"(b1));
}

// ---------------------------------------------------------------------------
// tf32 GEMM: out = X.W^T + bias (MODE 0) / res + relu(X.W^T + bias) (MODE 1)
// 128x128 tile, 8 warps as 4m x 2n; warp = 32 rows x 64 cols (2 strips, nt=8).
// X and W both staged ROW-major (stride 36 => conflict-free frag loads).
// ---------------------------------------------------------------------------
template<int MODE>
__global__ void __launch_bounds__(256) gemm_tc(
    const float* __restrict__ X, const float* __restrict__ W,
    const float* __restrict__ bias, const float* __restrict__ res,
    float* __restrict__ out)
{
    __shared__ unsigned Xs[128][36];   // [m][k]
    __shared__ unsigned Ws[128][36];   // [n][k]

    const int tid  = threadIdx.x;
    const int wid  = tid >> 5;
    const int lane = tid & 31;
    const int g    = lane >> 2;
    const int tig  = lane & 3;
    const int wm   = wid >> 1;          // 0..3
    const int wn   = wid & 1;           // 0..1
    const int m0   = blockIdx.x * 128;
    const int n0   = blockIdx.y * 128;

    float acc[2][8][4];
#pragma unroll
    for (int s = 0; s < 2; s++)
#pragma unroll
        for (int i = 0; i < 8; i++)
#pragma unroll
            for (int j = 0; j < 4; j++) acc[s][i][j] = 0.f;

    for (int k0 = 0; k0 < Dm; k0 += 32) {
        __syncthreads();
#pragma unroll
        for (int i = 0; i < 4; i++) {
            int idx = tid + 256 * i;
            int r   = idx >> 3;
            int c4  = (idx & 7) * 4;
            float4 xv = *(const float4*)&X[(size_t)(m0 + r) * Dm + k0 + c4];
            *(uint4*)&Xs[r][c4] =
                make_uint4(f2tf(xv.x), f2tf(xv.y), f2tf(xv.z), f2tf(xv.w));
            float4 wv = *(const float4*)&W[(size_t)(n0 + r) * Dm + k0 + c4];
            *(uint4*)&Ws[r][c4] =
                make_uint4(f2tf(wv.x), f2tf(wv.y), f2tf(wv.z), f2tf(wv.w));
        }
        __syncthreads();

#pragma unroll
        for (int kk = 0; kk < 4; kk++) {
            const int kb = kk * 8;
            unsigned a[2][4];
#pragma unroll
            for (int s = 0; s < 2; s++) {
                const int rr = wm * 32 + s * 16 + g;
                a[s][0] = Xs[rr][kb + tig];
                a[s][1] = Xs[rr + 8][kb + tig];
                a[s][2] = Xs[rr][kb + tig + 4];
                a[s][3] = Xs[rr + 8][kb + tig + 4];
            }
#pragma unroll
            for (int nt = 0; nt < 8; nt++) {
                const int nr = wn * 64 + nt * 8 + g;
                unsigned b0 = Ws[nr][kb + tig];
                unsigned b1 = Ws[nr][kb + tig + 4];
                mma8(acc[0][nt], a[0][0], a[0][1], a[0][2], a[0][3], b0, b1);
                mma8(acc[1][nt], a[1][0], a[1][1], a[1][2], a[1][3], b0, b1);
            }
        }
    }

#pragma unroll
    for (int s = 0; s < 2; s++) {
        const int r0 = m0 + wm * 32 + s * 16 + g;
        const int r1 = r0 + 8;
#pragma unroll
        for (int nt = 0; nt < 8; nt++) {
            const int n = n0 + wn * 64 + nt * 8 + 2 * tig;
            float2 bz = *(const float2*)&bias[n];
            float2 o0, o1;
            o0.x = acc[s][nt][0] + bz.x; o0.y = acc[s][nt][1] + bz.y;
            o1.x = acc[s][nt][2] + bz.x; o1.y = acc[s][nt][3] + bz.y;
            if (MODE == 1) {
                float2 q0 = *(const float2*)&res[(size_t)r0 * Dm + n];
                float2 q1 = *(const float2*)&res[(size_t)r1 * Dm + n];
                o0.x = q0.x + fmaxf(o0.x, 0.f); o0.y = q0.y + fmaxf(o0.y, 0.f);
                o1.x = q1.x + fmaxf(o1.x, 0.f); o1.y = q1.y + fmaxf(o1.y, 0.f);
            }
            *(float2*)&out[(size_t)r0 * Dm + n] = o0;
            *(float2*)&out[(size_t)r1 * Dm + n] = o1;
        }
    }
}

// ---------------------------------------------------------------------------
// tf32 flash attention: 128q x 128kv, 8 warps, warp owns 16 q rows.
// K and V staged row-major (no transpose, no conflicts). P never touches
// smem: S C-fragment -> PV A-fragment via quad shuffles. 2 CTAs/SM.
// ---------------------------------------------------------------------------
#define QS_STRIDE 68
#define KS_STRIDE 68
#define VS_STRIDE 72
#define QS_BASE 0
#define KS_BASE (QS_BASE + 128 * QS_STRIDE)
#define VS_BASE (KS_BASE + 128 * KS_STRIDE)
#define FLASH_SMEM_U32 (VS_BASE + 128 * VS_STRIDE)
#define FLASH_SMEM_BYTES (FLASH_SMEM_U32 * 4)

__global__ void __launch_bounds__(256, 2) flash_tc(
    const float* __restrict__ gQ, const float* __restrict__ gK,
    const float* __restrict__ gV, float* __restrict__ gO1)
{
    extern __shared__ unsigned sm[];
    unsigned* Qs = sm + QS_BASE;   // [128][68] q tf32, [m][d]
    unsigned* Ks = sm + KS_BASE;   // [128][68] k tf32, [kv][d]
    unsigned* Vs = sm + VS_BASE;   // [128][72] v tf32, [kv][d]

    const int tid  = threadIdx.x;
    const int wid  = tid >> 5;
    const int lane = tid & 31;
    const int g    = lane >> 2;
    const int tig  = lane & 3;

    const int bh = blockIdx.y;
    const int b  = bh / NHEADS;
    const int h  = bh % NHEADS;
    const int q0 = blockIdx.x * 128;

    const float* Qg = gQ + ((size_t)b * SQ + q0) * Dm + h * HDIM;
    const float* Kg = gK + (size_t)b * SQ * Dm + h * HDIM;
    const float* Vg = gV + (size_t)b * SQ * Dm + h * HDIM;

#pragma unroll
    for (int i = 0; i < 8; i++) {
        int idx = tid + 256 * i;
        int r   = idx >> 4;
        int c4  = (idx & 15) * 4;
        float4 v = *(const float4*)&Qg[(size_t)r * Dm + c4];
        *(uint4*)&Qs[r * QS_STRIDE + c4] =
            make_uint4(f2tf(v.x), f2tf(v.y), f2tf(v.z), f2tf(v.w));
    }

    float m0r = -1e30f, m1r = -1e30f, l0 = 0.f, l1 = 0.f;
    float oacc[8][4];
#pragma unroll
    for (int i = 0; i < 8; i++)
#pragma unroll
        for (int j = 0; j < 4; j++) oacc[i][j] = 0.f;

    const float SCL = ATT_SCALE * LOG2E;
    const int rw0 = 16 * wid + g;
    const int rw1 = rw0 + 8;
    const int s0lane = (lane & ~3) | (tig >> 1);   // 4g + tig/2
    const int s1lane = s0lane + 2;
    const bool odd = tig & 1;

    for (int kv0 = 0; kv0 < SQ; kv0 += 128) {
        __syncthreads();
#pragma unroll
        for (int i = 0; i < 8; i++) {
            int idx = tid + 256 * i;
            int r   = idx >> 4;
            int c4  = (idx & 15) * 4;
            float4 kv = *(const float4*)&Kg[(size_t)(kv0 + r) * Dm + c4];
            *(uint4*)&Ks[r * KS_STRIDE + c4] =
                make_uint4(f2tf(kv.x), f2tf(kv.y), f2tf(kv.z), f2tf(kv.w));
            float4 vv = *(const float4*)&Vg[(size_t)(kv0 + r) * Dm + c4];
            *(uint4*)&Vs[r * VS_STRIDE + c4] =
                make_uint4(f2tf(vv.x), f2tf(vv.y), f2tf(vv.z), f2tf(vv.w));
        }
        __syncthreads();

        // S = Q K^T
        float sacc[16][4];
#pragma unroll
        for (int i = 0; i < 16; i++)
#pragma unroll
            for (int j = 0; j < 4; j++) sacc[i][j] = 0.f;

#pragma unroll
        for (int ks = 0; ks < 8; ks++) {
            const int kb = ks * 8;
            unsigned a0 = Qs[rw0 * QS_STRIDE + kb + tig];
            unsigned a1 = Qs[rw1 * QS_STRIDE + kb + tig];
            unsigned a2 = Qs[rw0 * QS_STRIDE + kb + tig + 4];
            unsigned a3 = Qs[rw1 * QS_STRIDE + kb + tig + 4];
#pragma unroll
            for (int nt = 0; nt < 16; nt++) {
                unsigned b0 = Ks[(nt * 8 + g) * KS_STRIDE + kb + tig];
                unsigned b1 = Ks[(nt * 8 + g) * KS_STRIDE + kb + tig + 4];
                mma8(sacc[nt], a0, a1, a2, a3, b0, b1);
            }
        }

        // Online softmax (log2 domain), quad-lane row reduction
        float mx0 = -1e30f, mx1 = -1e30f;
#pragma unroll
        for (int nt = 0; nt < 16; nt++) {
            mx0 = fmaxf(mx0, fmaxf(sacc[nt][0], sacc[nt][1]));
            mx1 = fmaxf(mx1, fmaxf(sacc[nt][2], sacc[nt][3]));
        }
        mx0 *= SCL; mx1 *= SCL;
        mx0 = fmaxf(mx0, __shfl_xor_sync(0xffffffffu, mx0, 1));
        mx0 = fmaxf(mx0, __shfl_xor_sync(0xffffffffu, mx0, 2));
        mx1 = fmaxf(mx1, __shfl_xor_sync(0xffffffffu, mx1, 1));
        mx1 = fmaxf(mx1, __shfl_xor_sync(0xffffffffu, mx1, 2));

        float mn0 = fmaxf(m0r, mx0), mn1 = fmaxf(m1r, mx1);
        float al0 = exp2f(m0r - mn0), al1 = exp2f(m1r - mn1);
        m0r = mn0; m1r = mn1;

        float sum0 = 0.f, sum1 = 0.f;
#pragma unroll
        for (int nt = 0; nt < 16; nt++) {
            float p00 = exp2f(sacc[nt][0] * SCL - m0r);
            float p01 = exp2f(sacc[nt][1] * SCL - m0r);
            float p10 = exp2f(sacc[nt][2] * SCL - m1r);
            float p11 = exp2f(sacc[nt][3] * SCL - m1r);
            sum0 += p00 + p01;
            sum1 += p10 + p11;
            sacc[nt][0] = p00; sacc[nt][1] = p01;
            sacc[nt][2] = p10; sacc[nt][3] = p11;
        }
        sum0 += __shfl_xor_sync(0xffffffffu, sum0, 1);
        sum0 += __shfl_xor_sync(0xffffffffu, sum0, 2);
        sum1 += __shfl_xor_sync(0xffffffffu, sum1, 1);
        sum1 += __shfl_xor_sync(0xffffffffu, sum1, 2);
        l0 = l0 * al0 + sum0;
        l1 = l1 * al1 + sum1;

#pragma unroll
        for (int nt = 0; nt < 8; nt++) {
            oacc[nt][0] *= al0; oacc[nt][1] *= al0;
            oacc[nt][2] *= al1; oacc[nt][3] *= al1;
        }

        // O += P V : A-fragment built from S C-fragment via quad shuffles
#pragma unroll
        for (int ks = 0; ks < 16; ks++) {
            const int kb = ks * 8;
            float c0 = sacc[ks][0], c1 = sacc[ks][1];
            float c2 = sacc[ks][2], c3 = sacc[ks][3];
            float u00 = __shfl_sync(0xffffffffu, c0, s0lane);
            float u01 = __shfl_sync(0xffffffffu, c1, s0lane);
            float u10 = __shfl_sync(0xffffffffu, c0, s1lane);
            float u11 = __shfl_sync(0xffffffffu, c1, s1lane);
            float w00 = __shfl_sync(0xffffffffu, c2, s0lane);
            float w01 = __shfl_sync(0xffffffffu, c3, s0lane);
            float w10 = __shfl_sync(0xffffffffu, c2, s1lane);
            float w11 = __shfl_sync(0xffffffffu, c3, s1lane);
            unsigned a0 = f2tf(odd ? u01 : u00);
            unsigned a2 = f2tf(odd ? u11 : u10);
            unsigned a1 = f2tf(odd ? w01 : w00);
            unsigned a3 = f2tf(odd ? w11 : w10);
#pragma unroll
            for (int nt = 0; nt < 8; nt++) {
                unsigned b0 = Vs[(kb + tig) * VS_STRIDE + nt * 8 + g];
                unsigned b1 = Vs[(kb + tig + 4) * VS_STRIDE + nt * 8 + g];
                mma8(oacc[nt], a0, a1, a2, a3, b0, b1);
            }
        }
    }

    // Epilogue: out1 = q(fp32) + O/l
    float* Og = gO1 + ((size_t)b * SQ + q0) * Dm + h * HDIM;
    const float li0 = 1.f / l0, li1 = 1.f / l1;
#pragma unroll
    for (int nt = 0; nt < 8; nt++) {
        const int c = nt * 8 + 2 * tig;
        float2 q0v = *(const float2*)&Qg[(size_t)rw0 * Dm + c];
        float2 q1v = *(const float2*)&Qg[(size_t)rw1 * Dm + c];
        float2 o0, o1;
        o0.x = q0v.x + oacc[nt][0] * li0;
        o0.y = q0v.y + oacc[nt][1] * li0;
        o1.x = q1v.x + oacc[nt][2] * li1;
        o1.y = q1v.y + oacc[nt][3] * li1;
        *(float2*)&Og[(size_t)rw0 * Dm + c] = o0;
        *(float2*)&Og[(size_t)rw1 * Dm + c] = o1;
    }
}

// ---------------------------------------------------------------------------
extern "C" void kernel_launch(void* const* d_in, const int* in_sizes, int n_in,
                              void* d_out, int out_size)
{
    const float* query = (const float*)d_in[0];
    const float* keyv  = (const float*)d_in[1];
    const float* Wq    = (const float*)d_in[2];
    const float* bq    = (const float*)d_in[3];
    const float* Wk    = (const float*)d_in[4];
    const float* bk    = (const float*)d_in[5];
    const float* Wv    = (const float*)d_in[6];
    const float* bv    = (const float*)d_in[7];
    const float* Wo    = (const float*)d_in[8];
    const float* bo    = (const float*)d_in[9];
    float* out = (float*)d_out;

    float *qb, *kb, *vb, *o1;
    cudaGetSymbolAddress((void**)&qb, g_Q);
    cudaGetSymbolAddress((void**)&kb, g_K);
    cudaGetSymbolAddress((void**)&vb, g_V);
    cudaGetSymbolAddress((void**)&o1, g_O1);

    cudaFuncSetAttribute(flash_tc,
                         cudaFuncAttributeMaxDynamicSharedMemorySize,
                         FLASH_SMEM_BYTES);

    dim3 gg(MTOT / 128, Dm / 128);   // (64, 4)
    gemm_tc<0><<<gg, 256>>>(query, Wq, bq, nullptr, qb);
    gemm_tc<0><<<gg, 256>>>(keyv,  Wk, bk, nullptr, kb);
    gemm_tc<0><<<gg, 256>>>(keyv,  Wv, bv, nullptr, vb);

    dim3 ga(SQ / 128, 4 * NHEADS);   // (16, 32)
    flash_tc<<<ga, 256, FLASH_SMEM_BYTES>>>(qb, kb, vb, o1);

    gemm_tc<1><<<gg, 256>>>(o1, Wo, bo, o1, out);
}